// round 8
// baseline (speedup 1.0000x reference)
#include <cuda_runtime.h>
#include <float.h>

// features: [B=8, X=128, Y=128, C=128] f32   (C contiguous)
// rois:     [B, N=128, 4] i32  (minX, minY, maxX, maxY)
// out:      [B, N, 7, 7, C] f32
//
// Two-pass pyramid:
//   Pass 1: P1[b][x][y][c] = max(f[x..x+1][y..y+1])   (sliding 2x2 max)
//   Pass 2: bin (>=2x2 guaranteed) = max over P1 at stride-2 positions:
//           n>>1 unclamped samples + one tail sample at n-2 iff n is odd.

#define PH 7
#define PW 7
#define B_ 8
#define N_ 128
#define XDIM 128
#define YDIM 128
#define C4   32                  // 32 float4 per pixel (C=128)
#define COLS (YDIM * C4)         // float4 stride for +1 in x (4096)

// 64 MB scratch: [b][x][y][c4] float4
__device__ float4 d_P1[B_ * XDIM * YDIM * C4];

__device__ __forceinline__ float4 f4max(float4 a, float4 b) {
    return make_float4(fmaxf(a.x, b.x), fmaxf(a.y, b.y),
                       fmaxf(a.z, b.z), fmaxf(a.w, b.w));
}

// ---------------- Pass 1: sliding 2x2 max, 4 output rows per warp ----------
// warp -> (b, xg, yc): outputs x in [4*xg, 4*xg+4), y in [8*yc, 8*yc+8).
// Loads 5 input rows once each (register carry in y): 80 MB read total.
#define P1_XR 4
#define P1_YS 8
#define P1_WPB 8

__global__ __launch_bounds__(P1_WPB * 32)
void build_p1_kernel(const float4* __restrict__ f)
{
    int gw   = blockIdx.x * P1_WPB + (threadIdx.x >> 5);
    int lane = threadIdx.x & 31;

    int yc = gw & 15;            // 16 y-chunks
    int t  = gw >> 4;
    int xg = t & 31;             // 32 x-groups
    int b  = t >> 5;
    int y0 = yc * P1_YS;
    int x0 = xg * P1_XR;

    const float4* p0 = f + (b * XDIM + x0) * COLS + y0 * C4 + lane;
    const float4* p1 = p0 + COLS;
    const float4* p2 = p1 + COLS;
    const float4* p3 = p2 + COLS;
    // row x0+4 clamped to 127 (only xg==31 clamps; that output column is junk
    // scratch never read by pass 2 since sample x <= maxX-2 <= 124)
    const float4* p4 = f + (b * XDIM + min(x0 + 4, XDIM - 1)) * COLS + y0 * C4 + lane;

    float4* o = d_P1 + (b * XDIM + x0) * COLS + y0 * C4 + lane;

    int ymax = (YDIM - 1) - y0;  // clamp next-row load to y=127

    float4 c0 = p0[0], c1 = p1[0], c2 = p2[0], c3 = p3[0], c4 = p4[0];

    #pragma unroll
    for (int i = 0; i < P1_YS; ++i) {
        int off = min(i + 1, ymax) * C4;
        float4 n0 = p0[off];
        float4 n1 = p1[off];
        float4 n2 = p2[off];
        float4 n3 = p3[off];
        float4 n4 = p4[off];
        o[0 * COLS + i * C4] = f4max(f4max(c0, c1), f4max(n0, n1));
        o[1 * COLS + i * C4] = f4max(f4max(c1, c2), f4max(n1, n2));
        o[2 * COLS + i * C4] = f4max(f4max(c2, c3), f4max(n2, n3));
        o[3 * COLS + i * C4] = f4max(f4max(c3, c4), f4max(n3, n4));
        c0 = n0; c1 = n1; c2 = n2; c3 = n3; c4 = n4;
    }
}

// ---------------- Pass 2: ROI pooling from P1 (no clamps) ----------------
// One sample column: uy unclamped samples at y offsets 0,2C4,... plus tail
// at ytail iff ny odd. All branches warp-uniform.
__device__ __forceinline__ void scol(const float4* __restrict__ p,
                                     int uy, int ytail, int yodd,
                                     float4& m0, float4& m1)
{
    int i = 0;
    for (; i + 2 <= uy; i += 2) {
        float4 a0 = p[(2 * i) * C4];
        float4 a1 = p[(2 * i + 2) * C4];
        m0 = f4max(m0, a0);
        m1 = f4max(m1, a1);
    }
    if (i < uy) m0 = f4max(m0, p[(2 * i) * C4]);
    if (yodd)   m1 = f4max(m1, p[ytail]);
}

__global__ __launch_bounds__(PW * 32)
void roi_pool_p1_kernel(const int4* __restrict__ rois,
                        float4*     __restrict__ out)
{
    int bid  = blockIdx.x;
    int h    = bid % PH;
    int t    = bid / PH;          // t = b*N_ + n
    int b    = t >> 7;            // / N_
    int w    = threadIdx.x >> 5;
    int lane = threadIdx.x & 31;

    const int4 r = rois[t];
    int dx = (r.z - r.x) / PW;
    int dy = (r.w - r.y) / PH;

    int y0 = r.y + h * dy;
    int ny = (h == PH - 1) ? (r.w - y0) : dy;    // >= 2
    int x0 = r.x + w * dx;
    int nx = (w == PW - 1) ? (r.z - x0) : dx;    // >= 2

    int ux = nx >> 1, uy = ny >> 1;
    int ytail = (ny - 2) * C4;
    int yodd  = ny & 1;

    const float4* base = d_P1 + (b * XDIM + x0) * COLS + y0 * C4 + lane;

    const float4 NEG = make_float4(-FLT_MAX, -FLT_MAX, -FLT_MAX, -FLT_MAX);
    float4 m0 = NEG, m1 = NEG, m2 = NEG, m3 = NEG;

    int j = 0;
    for (; j + 2 <= ux; j += 2) {
        scol(base + (2 * j)     * COLS, uy, ytail, yodd, m0, m1);
        scol(base + (2 * j + 2) * COLS, uy, ytail, yodd, m2, m3);
    }
    if (j < ux)
        scol(base + (2 * j) * COLS, uy, ytail, yodd, m0, m1);
    if (nx & 1)
        scol(base + (nx - 2) * COLS, uy, ytail, yodd, m2, m3);

    float4 m = f4max(f4max(m0, m1), f4max(m2, m3));
    out[(bid * PW + w) * C4 + lane] = m;          // bid = t*PH + h
}

extern "C" void kernel_launch(void* const* d_in, const int* in_sizes, int n_in,
                              void* d_out, int out_size)
{
    const float4* features = (const float4*)d_in[0];
    const int4*   rois     = (const int4*)d_in[1];
    float4*       out      = (float4*)d_out;

    // Pass 1: 8*32*16 = 4096 warps -> 512 blocks of 8 warps
    dim3 grid1(B_ * 32 * 16 / P1_WPB);
    dim3 block1(P1_WPB * 32);
    build_p1_kernel<<<grid1, block1>>>(features);

    // Pass 2
    dim3 grid2(B_ * N_ * PH);                      // 7168
    dim3 block2(PW * 32);                          // 224
    roi_pool_p1_kernel<<<grid2, block2>>>(rois, out);
}